// round 2
// baseline (speedup 1.0000x reference)
#include <cuda_runtime.h>
#include <math.h>

// Problem constants (fixed by the dataset)
#define NN 50000
#define EE 500000
#define ET (EE + NN)
#define NBLK ((NN + 255) / 256)

// ---------------- scratch (device globals; no runtime allocation) ----------------
__device__ __align__(16) float g_h1[NN * 256];
__device__ __align__(16) float g_x1[NN * 256];
__device__ __align__(16) float g_h2[NN * 128];
__device__ __align__(16) float g_x2[NN * 128];
__device__ float g_asrc1[NN * 2], g_adst1[NN * 2];
__device__ float g_asrc2[NN], g_adst2[NN];
__device__ __align__(16) float g_yl[NN * 96];
__device__ __align__(16) float g_ya[NN * 96];
__device__ __align__(16) float g_yb[NN * 2];
__device__ float g_statL[192], g_statA[192], g_statB[4];
__device__ float g_scaleL[96], g_shiftL[96];
__device__ float g_scaleA[96], g_shiftA[96];
__device__ float g_scaleB[2], g_shiftB[2];
__device__ int g_is64;
// CSR
__device__ int g_deg[NN];
__device__ int g_row_ptr[NN + 1];
__device__ int g_cursor[NN];
__device__ int g_csr_src[ET];
__device__ int g_partials[NBLK + 1];

// ---------------- edge loading (int64 or int32 edge_index) ----------------
__device__ __forceinline__ void load_edge(const void* ei, int e, int E, int& s, int& d) {
    if (e >= E) { s = d = e - E; return; }
    if (g_is64) {
        const long long* p = (const long long*)ei;
        s = (int)p[e];
        d = (int)p[E + e];
    } else {
        const int* p = (const int*)ei;
        s = p[e];
        d = p[E + e];
    }
}

__global__ void detect_kernel(const int* ei32) {
    __shared__ int found;
    if (threadIdx.x == 0) found = 0;
    __syncthreads();
    for (int i = threadIdx.x; i < 4096; i += blockDim.x)
        if (ei32[2 * i + 1] != 0) found = 1;
    __syncthreads();
    if (threadIdx.x == 0) g_is64 = (found == 0) ? 1 : 0;
}

__global__ void init_kernel(int n) {
    int i = blockIdx.x * blockDim.x + threadIdx.x;
    if (i < n) g_deg[i] = 0;
    if (i < 192) { g_statL[i] = 0.f; g_statA[i] = 0.f; }
    if (i < 4) g_statB[i] = 0.f;
}

// ---------------- CSR build ----------------
__global__ void csr_count_kernel(const void* ei, int E, int n) {
    int e = blockIdx.x * blockDim.x + threadIdx.x;
    if (e >= E + n) return;
    int s, d; load_edge(ei, e, E, s, d);
    (void)s;
    atomicAdd(&g_deg[d], 1);
}

__global__ void block_sum_kernel(int n) {
    __shared__ int sm[256];
    int i = blockIdx.x * 256 + threadIdx.x;
    sm[threadIdx.x] = (i < n) ? g_deg[i] : 0;
    __syncthreads();
    for (int off = 128; off; off >>= 1) {
        if (threadIdx.x < off) sm[threadIdx.x] += sm[threadIdx.x + off];
        __syncthreads();
    }
    if (threadIdx.x == 0) g_partials[blockIdx.x] = sm[0];
}

__global__ void scan_partials_kernel(int nblk, int etot, int n) {
    __shared__ int sm[256];
    int t = threadIdx.x;
    int v = (t < nblk) ? g_partials[t] : 0;
    sm[t] = v;
    __syncthreads();
    #pragma unroll
    for (int off = 1; off < 256; off <<= 1) {
        int x = (t >= off) ? sm[t - off] : 0;
        __syncthreads();
        sm[t] += x;
        __syncthreads();
    }
    if (t < nblk) g_partials[t] = sm[t] - v;   // exclusive
    if (t == 0) g_row_ptr[n] = etot;
}

__global__ void scan_final_kernel(int n) {
    __shared__ int sm[256];
    int t = threadIdx.x;
    int i = blockIdx.x * 256 + t;
    int v = (i < n) ? g_deg[i] : 0;
    sm[t] = v;
    __syncthreads();
    #pragma unroll
    for (int off = 1; off < 256; off <<= 1) {
        int x = (t >= off) ? sm[t - off] : 0;
        __syncthreads();
        sm[t] += x;
        __syncthreads();
    }
    if (i < n) {
        int rp = g_partials[blockIdx.x] + sm[t] - v;
        g_row_ptr[i] = rp;
        g_cursor[i] = rp;
    }
}

__global__ void csr_fill_kernel(const void* ei, int E, int n) {
    int e = blockIdx.x * blockDim.x + threadIdx.x;
    if (e >= E + n) return;
    int s, d; load_edge(ei, e, E, s, d);
    int pos = atomicAdd(&g_cursor[d], 1);
    g_csr_src[pos] = s;
}

// ---------------- fp32 tiled GEMM: 128x64x16, 8x4 per thread ----------------
#define GBM 128
#define GBN 64
#define GBK 16
template<bool RELU>
__global__ void gemm_kernel(const float* __restrict__ A1, int K1,
                            const float* __restrict__ A2, int K2,
                            const float* __restrict__ B,
                            const float* __restrict__ bias,
                            const float* __restrict__ a_scale,
                            const float* __restrict__ a_shift,
                            float* __restrict__ C,
                            int M, int N, int K)
{
    __shared__ float As[GBK][GBM + 4];
    __shared__ float Bs[GBK][GBN + 4];
    int tid = threadIdx.x;                 // 256 threads
    int bm0 = blockIdx.y * GBM;
    int bn0 = blockIdx.x * GBN;
    int tx = tid & 15, ty = tid >> 4;      // 16x16; thread tile 8 rows x 4 cols
    float acc[8][4] = {};

    for (int k0 = 0; k0 < K; k0 += GBK) {
        #pragma unroll
        for (int i = 0; i < 8; i++) {
            int r = (tid >> 4) + i * 16;
            int c = tid & 15;
            int row = bm0 + r, kk = k0 + c;
            float v = 0.f;
            if (row < M) {
                v = (kk < K1) ? A1[(size_t)row * K1 + kk]
                              : A2[(size_t)row * K2 + (kk - K1)];
                if (a_scale) v = fmaf(v, a_scale[kk], a_shift[kk]);
            }
            As[c][r] = v;
        }
        #pragma unroll
        for (int i = 0; i < 4; i++) {
            int c = tid & 63;
            int r = (tid >> 6) + i * 4;
            int col = bn0 + c;
            Bs[r][c] = (col < N) ? B[(size_t)(k0 + r) * N + col] : 0.f;
        }
        __syncthreads();
        #pragma unroll
        for (int kk = 0; kk < GBK; kk++) {
            float4 a0 = *(const float4*)&As[kk][ty * 8];
            float4 a1 = *(const float4*)&As[kk][ty * 8 + 4];
            float4 b  = *(const float4*)&Bs[kk][tx * 4];
            float av[8] = {a0.x, a0.y, a0.z, a0.w, a1.x, a1.y, a1.z, a1.w};
            float bv[4] = {b.x, b.y, b.z, b.w};
            #pragma unroll
            for (int i = 0; i < 8; i++)
                #pragma unroll
                for (int j = 0; j < 4; j++)
                    acc[i][j] = fmaf(av[i], bv[j], acc[i][j]);
        }
        __syncthreads();
    }

    #pragma unroll
    for (int i = 0; i < 8; i++) {
        int row = bm0 + ty * 8 + i;
        if (row >= M) continue;
        #pragma unroll
        for (int j = 0; j < 4; j++) {
            int col = bn0 + tx * 4 + j;
            if (col >= N) continue;
            float v = acc[i][j];
            if (bias) v += bias[col];
            if (RELU) v = fmaxf(v, 0.f);
            C[(size_t)row * N + col] = v;
        }
    }
}

// ---------------- attention source/dest logits: warp per node ----------------
template<int HEADS>
__global__ void att_dots_kernel(const float* __restrict__ h,
                                const float* __restrict__ att_src,
                                const float* __restrict__ att_dst,
                                float* __restrict__ asrc, float* __restrict__ adst, int n)
{
    int warp = (blockIdx.x * blockDim.x + threadIdx.x) >> 5;
    int lane = threadIdx.x & 31;
    if (warp >= n) return;
    const float* row = h + (size_t)warp * (HEADS * 128);
    #pragma unroll
    for (int hd = 0; hd < HEADS; hd++) {
        float ss = 0.f, sd = 0.f;
        #pragma unroll
        for (int c = lane; c < 128; c += 32) {
            float v = row[hd * 128 + c];
            ss = fmaf(v, att_src[hd * 128 + c], ss);
            sd = fmaf(v, att_dst[hd * 128 + c], sd);
        }
        #pragma unroll
        for (int o = 16; o; o >>= 1) {
            ss += __shfl_xor_sync(0xffffffffu, ss, o);
            sd += __shfl_xor_sync(0xffffffffu, sd, o);
        }
        if (lane == 0) {
            asrc[warp * HEADS + hd] = ss;
            adst[warp * HEADS + hd] = sd;
        }
    }
}

// ---------------- fused per-node softmax aggregation (CSR, warp per node) ----------
template<int HEADS>
__global__ void agg_kernel(const float* __restrict__ h,
                           const float* __restrict__ asrc,
                           const float* __restrict__ adst,
                           const float* __restrict__ bias,
                           float* __restrict__ out, int n)
{
    int d = (int)((((size_t)blockIdx.x * blockDim.x) + threadIdx.x) >> 5);
    int lane = threadIdx.x & 31;
    if (d >= n) return;
    int r0 = g_row_ptr[d];
    int r1 = g_row_ptr[d + 1];

    float ad0, ad1 = 0.f;
    if (HEADS == 2) {
        float2 t = ((const float2*)adst)[d];
        ad0 = t.x; ad1 = t.y;
    } else {
        ad0 = adst[d];
    }

    // phase 1: per-head max over incident edges
    const float NEG_INF = __int_as_float(0xff800000);
    float m0 = NEG_INF, m1 = NEG_INF;
    for (int k = r0 + lane; k < r1; k += 32) {
        int s = g_csr_src[k];
        if (HEADS == 2) {
            float2 as2 = ((const float2*)asrc)[s];
            float a0 = as2.x + ad0;
            float a1 = as2.y + ad1;
            a0 = (a0 > 0.f) ? a0 : 0.2f * a0;
            a1 = (a1 > 0.f) ? a1 : 0.2f * a1;
            m0 = fmaxf(m0, a0);
            m1 = fmaxf(m1, a1);
        } else {
            float a0 = asrc[s] + ad0;
            a0 = (a0 > 0.f) ? a0 : 0.2f * a0;
            m0 = fmaxf(m0, a0);
        }
    }
    #pragma unroll
    for (int o = 16; o; o >>= 1) {
        m0 = fmaxf(m0, __shfl_xor_sync(0xffffffffu, m0, o));
        if (HEADS == 2) m1 = fmaxf(m1, __shfl_xor_sync(0xffffffffu, m1, o));
    }

    // phase 2: accumulate unnormalized weighted sum + partition sum
    const int CPL = HEADS * 128 / 32;     // 8 (conv1) or 4 (conv2)
    int c0 = lane * CPL;
    int hd = (HEADS == 2) ? (lane >> 4) : 0;
    float myad = (hd == 0) ? ad0 : ad1;
    float mym = (hd == 0) ? m0 : m1;

    float acc[CPL];
    #pragma unroll
    for (int j = 0; j < CPL; j++) acc[j] = 0.f;
    float ssum = 0.f;

    int k = r0;
    int sNext = g_csr_src[k];
    while (k < r1) {
        int s = sNext;
        k++;
        if (k < r1) sNext = g_csr_src[k];
        float a;
        if (HEADS == 2) {
            float2 as2 = ((const float2*)asrc)[s];
            a = ((hd == 0) ? as2.x : as2.y) + myad;
        } else {
            a = asrc[s] + myad;
        }
        a = (a > 0.f) ? a : 0.2f * a;
        float w = __expf(a - mym);
        ssum += w;
        const float4* hp = (const float4*)(h + (size_t)s * (HEADS * 128) + c0);
        #pragma unroll
        for (int v = 0; v < CPL / 4; v++) {
            float4 t = hp[v];
            acc[v * 4 + 0] = fmaf(w, t.x, acc[v * 4 + 0]);
            acc[v * 4 + 1] = fmaf(w, t.y, acc[v * 4 + 1]);
            acc[v * 4 + 2] = fmaf(w, t.z, acc[v * 4 + 2]);
            acc[v * 4 + 3] = fmaf(w, t.w, acc[v * 4 + 3]);
        }
    }

    float inv = 1.f / (ssum + 1e-16f);
    float* op = out + (size_t)d * (HEADS * 128) + c0;
    #pragma unroll
    for (int j = 0; j < CPL; j++)
        op[j] = fmaf(acc[j], inv, bias[c0 + j]);
}

// ---------------- batchnorm stats ----------------
__global__ void stats_cols_kernel(const float* __restrict__ y, int M, int ncols,
                                  float* __restrict__ stats)
{
    int col = threadIdx.x;          // blockDim.x == ncols
    float s = 0.f, ss = 0.f;
    for (int r = blockIdx.x; r < M; r += gridDim.x) {
        float v = y[(size_t)r * ncols + col];
        s += v; ss = fmaf(v, v, ss);
    }
    atomicAdd(&stats[col], s);
    atomicAdd(&stats[ncols + col], ss);
}

__global__ void bn_finalize_kernel(const float* __restrict__ stats,
                                   const float* __restrict__ gamma,
                                   const float* __restrict__ beta,
                                   float* __restrict__ scale, float* __restrict__ shift,
                                   int M, int ncols)
{
    int c = threadIdx.x;
    if (c >= ncols) return;
    float inv = 1.f / (float)M;
    float mu = stats[c] * inv;
    float var = stats[ncols + c] * inv - mu * mu;
    float sc = gamma[c] * rsqrtf(var + 1e-5f);
    scale[c] = sc;
    shift[c] = beta[c] - mu * sc;
}

// ---------------- fused last Linear (96->2) + relu + stats ----------------
__global__ void mlpb_kernel(const float* __restrict__ ya,
                            const float* __restrict__ scaleA,
                            const float* __restrict__ shiftA,
                            const float* __restrict__ Wb,
                            const float* __restrict__ bb,
                            float* __restrict__ yb,
                            float* __restrict__ stats, int M)
{
    __shared__ float w[192];
    __shared__ float sA[96], sS[96], bsh[2];
    int t = threadIdx.x;
    if (t < 192) w[t] = Wb[t];                  // [96,2] row-major
    if (t < 96) { sA[t] = scaleA[t]; sS[t] = shiftA[t]; }
    if (t < 2) bsh[t] = bb[t];
    __syncthreads();

    int r = blockIdx.x * blockDim.x + t;
    float y0 = 0.f, y1 = 0.f;
    if (r < M) {
        const float4* row = (const float4*)(ya + (size_t)r * 96);
        float acc0 = bsh[0], acc1 = bsh[1];
        #pragma unroll
        for (int v = 0; v < 24; v++) {
            float4 q = row[v];
            float vals[4] = {q.x, q.y, q.z, q.w};
            #pragma unroll
            for (int j = 0; j < 4; j++) {
                int c = v * 4 + j;
                float z = fmaf(vals[j], sA[c], sS[c]);
                acc0 = fmaf(z, w[c * 2], acc0);
                acc1 = fmaf(z, w[c * 2 + 1], acc1);
            }
        }
        y0 = fmaxf(acc0, 0.f);
        y1 = fmaxf(acc1, 0.f);
        yb[r * 2] = y0;
        yb[r * 2 + 1] = y1;
    }
    float s0 = y0, ss0 = y0 * y0, s1 = y1, ss1 = y1 * y1;
    #pragma unroll
    for (int o = 16; o; o >>= 1) {
        s0  += __shfl_xor_sync(0xffffffffu, s0, o);
        ss0 += __shfl_xor_sync(0xffffffffu, ss0, o);
        s1  += __shfl_xor_sync(0xffffffffu, s1, o);
        ss1 += __shfl_xor_sync(0xffffffffu, ss1, o);
    }
    if ((t & 31) == 0) {
        atomicAdd(&stats[0], s0);
        atomicAdd(&stats[1], s1);
        atomicAdd(&stats[2], ss0);
        atomicAdd(&stats[3], ss1);
    }
}

__global__ void final_kernel(const float* __restrict__ yb,
                             const float* __restrict__ scale,
                             const float* __restrict__ shift,
                             float* __restrict__ out, int total)
{
    int i = blockIdx.x * blockDim.x + threadIdx.x;
    if (i < total) {
        int c = i & 1;
        out[i] = fmaf(scale[c], yb[i], shift[c]);
    }
}

// ---------------- launch ----------------
static inline void* sym(const void* s) {
    void* p = nullptr;
    cudaGetSymbolAddress(&p, s);
    return p;
}

extern "C" void kernel_launch(void* const* d_in, const int* in_sizes, int n_in,
                              void* d_out, int out_size)
{
    const float* x        = (const float*)d_in[0];
    const void*  ei       = d_in[1];
    const float* W1       = (const float*)d_in[2];
    const float* att_src1 = (const float*)d_in[3];
    const float* att_dst1 = (const float*)d_in[4];
    const float* bias1    = (const float*)d_in[5];
    const float* W2       = (const float*)d_in[6];
    const float* att_src2 = (const float*)d_in[7];
    const float* att_dst2 = (const float*)d_in[8];
    const float* bias2    = (const float*)d_in[9];
    const float* Wl = (const float*)d_in[10];
    const float* bl = (const float*)d_in[11];
    const float* gl = (const float*)d_in[12];
    const float* betal = (const float*)d_in[13];
    const float* Wa = (const float*)d_in[14];
    const float* ba = (const float*)d_in[15];
    const float* ga = (const float*)d_in[16];
    const float* betaa = (const float*)d_in[17];
    const float* Wb = (const float*)d_in[18];
    const float* bb = (const float*)d_in[19];
    const float* gb = (const float*)d_in[20];
    const float* betab = (const float*)d_in[21];
    float* out = (float*)d_out;

    int n = in_sizes[0] / 128;      // 50000
    int E = in_sizes[1] / 2;        // 500000
    int Etot = E + n;
    int nblk = (n + 255) / 256;

    float* h1 = (float*)sym(g_h1);
    float* x1 = (float*)sym(g_x1);
    float* h2 = (float*)sym(g_h2);
    float* x2 = (float*)sym(g_x2);
    float* asrc1 = (float*)sym(g_asrc1);
    float* adst1 = (float*)sym(g_adst1);
    float* asrc2 = (float*)sym(g_asrc2);
    float* adst2 = (float*)sym(g_adst2);
    float* yl = (float*)sym(g_yl);
    float* ya = (float*)sym(g_ya);
    float* yb = (float*)sym(g_yb);
    float* statL = (float*)sym(g_statL);
    float* statA = (float*)sym(g_statA);
    float* statB = (float*)sym(g_statB);
    float* scaleL = (float*)sym(g_scaleL);
    float* shiftL = (float*)sym(g_shiftL);
    float* scaleA = (float*)sym(g_scaleA);
    float* shiftA = (float*)sym(g_shiftA);
    float* scaleB = (float*)sym(g_scaleB);
    float* shiftB = (float*)sym(g_shiftB);

    int edge_blocks = (Etot + 255) / 256;
    int warp_blocks = (n + 7) / 8;

    // 0) dtype detect + zero accumulators
    detect_kernel<<<1, 256>>>((const int*)ei);
    init_kernel<<<(n + 255) / 256, 256>>>(n);

    // 1) CSR build (shared by both conv layers)
    csr_count_kernel<<<edge_blocks, 256>>>(ei, E, n);
    block_sum_kernel<<<nblk, 256>>>(n);
    scan_partials_kernel<<<1, 256>>>(nblk, Etot, n);
    scan_final_kernel<<<nblk, 256>>>(n);
    csr_fill_kernel<<<edge_blocks, 256>>>(ei, E, n);

    // ---------- conv1 ----------
    {
        dim3 grid((256 + GBN - 1) / GBN, (n + GBM - 1) / GBM);
        gemm_kernel<false><<<grid, 256>>>(x, 128, x, 128, W1, nullptr, nullptr, nullptr,
                                          h1, n, 256, 128);
    }
    att_dots_kernel<2><<<warp_blocks, 256>>>(h1, att_src1, att_dst1, asrc1, adst1, n);
    agg_kernel<2><<<warp_blocks, 256>>>(h1, asrc1, adst1, bias1, x1, n);

    // ---------- conv2 ----------
    {
        dim3 grid((128 + GBN - 1) / GBN, (n + GBM - 1) / GBM);
        gemm_kernel<false><<<grid, 256>>>(x1, 256, x1, 256, W2, nullptr, nullptr, nullptr,
                                          h2, n, 128, 256);
    }
    att_dots_kernel<1><<<warp_blocks, 256>>>(h2, att_src2, att_dst2, asrc2, adst2, n);
    agg_kernel<1><<<warp_blocks, 256>>>(h2, asrc2, adst2, bias2, x2, n);

    // ---------- MLP head ----------
    {
        dim3 grid((96 + GBN - 1) / GBN, (n + GBM - 1) / GBM);
        gemm_kernel<true><<<grid, 256>>>(x1, 256, x2, 128, Wl, bl, nullptr, nullptr,
                                         yl, n, 96, 384);
    }
    stats_cols_kernel<<<512, 96>>>(yl, n, 96, statL);
    bn_finalize_kernel<<<1, 96>>>(statL, gl, betal, scaleL, shiftL, n, 96);

    {
        dim3 grid((96 + GBN - 1) / GBN, (n + GBM - 1) / GBM);
        gemm_kernel<true><<<grid, 256>>>(yl, 96, yl, 96, Wa, ba, scaleL, shiftL,
                                         ya, n, 96, 96);
    }
    stats_cols_kernel<<<512, 96>>>(ya, n, 96, statA);
    bn_finalize_kernel<<<1, 96>>>(statA, ga, betaa, scaleA, shiftA, n, 96);

    mlpb_kernel<<<(n + 255) / 256, 256>>>(ya, scaleA, shiftA, Wb, bb, yb, statB, n);
    bn_finalize_kernel<<<1, 2>>>(statB, gb, betab, scaleB, shiftB, n, 2);

    final_kernel<<<(n * 2 + 255) / 256, 256>>>(yb, scaleB, shiftB, out, n * 2);
}

// round 3
// speedup vs baseline: 2.3636x; 2.3636x over previous
#include <cuda_runtime.h>
#include <math.h>
#include <stdint.h>

// Problem constants (fixed by the dataset)
#define NN 50000
#define EE 500000
#define ET (EE + NN)
#define NBLK ((NN + 255) / 256)

// ---------------- scratch (device globals; no runtime allocation) ----------------
__device__ __align__(16) float g_h1[NN * 256];
__device__ __align__(16) float g_x1[NN * 256];
__device__ __align__(16) float g_h2[NN * 128];
__device__ __align__(16) float g_x2[NN * 128];
__device__ float g_asrc1[NN * 2], g_adst1[NN * 2];
__device__ float g_asrc2[NN], g_adst2[NN];
__device__ __align__(16) float g_yl[NN * 96];
__device__ __align__(16) float g_ya[NN * 96];
__device__ __align__(16) float g_yb[NN * 2];
__device__ float g_statL[192], g_statA[192], g_statB[4];
__device__ float g_scaleL[96], g_shiftL[96];
__device__ float g_scaleA[96], g_shiftA[96];
__device__ float g_scaleB[2], g_shiftB[2];
__device__ int g_is64;
// CSR
__device__ int g_deg[NN];
__device__ int g_row_ptr[NN + 1];
__device__ int g_cursor[NN];
__device__ int g_csr_src[ET];
__device__ int g_partials[NBLK + 1];

// ---------------- edge loading (int64 or int32 edge_index) ----------------
__device__ __forceinline__ void load_edge(const void* ei, int e, int E, int& s, int& d) {
    if (e >= E) { s = d = e - E; return; }
    if (g_is64) {
        const long long* p = (const long long*)ei;
        s = (int)p[e];
        d = (int)p[E + e];
    } else {
        const int* p = (const int*)ei;
        s = p[e];
        d = p[E + e];
    }
}

// detect int64 vs int32 + zero accumulators (fused)
__global__ void detect_init_kernel(const int* ei32, int n) {
    int i = blockIdx.x * blockDim.x + threadIdx.x;
    if (i < n) g_deg[i] = 0;
    if (i < 192) { g_statL[i] = 0.f; g_statA[i] = 0.f; }
    if (i < 4) g_statB[i] = 0.f;
    if (blockIdx.x == 0) {
        __shared__ int found;
        if (threadIdx.x == 0) found = 0;
        __syncthreads();
        for (int j = threadIdx.x; j < 4096; j += blockDim.x)
            if (ei32[2 * j + 1] != 0) found = 1;
        __syncthreads();
        if (threadIdx.x == 0) g_is64 = (found == 0) ? 1 : 0;
    }
}

// ---------------- CSR build ----------------
__global__ void csr_count_kernel(const void* ei, int E, int n) {
    int e = blockIdx.x * blockDim.x + threadIdx.x;
    if (e >= E + n) return;
    int s, d; load_edge(ei, e, E, s, d);
    (void)s;
    atomicAdd(&g_deg[d], 1);
}

__global__ void block_sum_kernel(int n) {
    __shared__ int sm[256];
    int i = blockIdx.x * 256 + threadIdx.x;
    sm[threadIdx.x] = (i < n) ? g_deg[i] : 0;
    __syncthreads();
    for (int off = 128; off; off >>= 1) {
        if (threadIdx.x < off) sm[threadIdx.x] += sm[threadIdx.x + off];
        __syncthreads();
    }
    if (threadIdx.x == 0) g_partials[blockIdx.x] = sm[0];
}

__global__ void scan_partials_kernel(int nblk, int etot, int n) {
    __shared__ int sm[256];
    int t = threadIdx.x;
    int v = (t < nblk) ? g_partials[t] : 0;
    sm[t] = v;
    __syncthreads();
    #pragma unroll
    for (int off = 1; off < 256; off <<= 1) {
        int x = (t >= off) ? sm[t - off] : 0;
        __syncthreads();
        sm[t] += x;
        __syncthreads();
    }
    if (t < nblk) g_partials[t] = sm[t] - v;   // exclusive
    if (t == 0) g_row_ptr[n] = etot;
}

__global__ void scan_final_kernel(int n) {
    __shared__ int sm[256];
    int t = threadIdx.x;
    int i = blockIdx.x * 256 + t;
    int v = (i < n) ? g_deg[i] : 0;
    sm[t] = v;
    __syncthreads();
    #pragma unroll
    for (int off = 1; off < 256; off <<= 1) {
        int x = (t >= off) ? sm[t - off] : 0;
        __syncthreads();
        sm[t] += x;
        __syncthreads();
    }
    if (i < n) {
        int rp = g_partials[blockIdx.x] + sm[t] - v;
        g_row_ptr[i] = rp;
        g_cursor[i] = rp;
    }
}

__global__ void csr_fill_kernel(const void* ei, int E, int n) {
    int e = blockIdx.x * blockDim.x + threadIdx.x;
    if (e >= E + n) return;
    int s, d; load_edge(ei, e, E, s, d);
    int pos = atomicAdd(&g_cursor[d], 1);
    g_csr_src[pos] = s;
}

// ---------------- tf32 tensor-core GEMM: 128x64 block, mma.sync.m16n8k8 ----------
__device__ __forceinline__ float to_tf32(float v) {
    asm("cvt.rna.tf32.f32 %0, %1;" : "=f"(v) : "f"(v));
    return v;
}

template<bool RELU>
__global__ __launch_bounds__(256, 3)
void gemm_tc(const float* __restrict__ A1, int K1,
             const float* __restrict__ A2, int K2,
             const float* __restrict__ B,
             const float* __restrict__ bias,
             const float* __restrict__ a_scale,
             const float* __restrict__ a_shift,
             float* __restrict__ C,
             int M, int N, int K)
{
    __shared__ float As[128][20];   // [m][k], stride 20 -> conflict-free frags
    __shared__ float Bs[16][72];    // [k][n], stride 72 -> conflict-free frags
    int tid = threadIdx.x;
    int lane = tid & 31, warp = tid >> 5;
    int warpM = warp & 3, warpN = warp >> 1 & 1; // 4 M-bands x 2 N-bands
    warpN = warp >> 2;                            // warps 0-3 -> N band 0, 4-7 -> band 1
    int bm0 = blockIdx.y * 128, bn0 = blockIdx.x * 64;
    int lr = lane >> 2, lc = lane & 3;
    float acc[2][4][4];
    #pragma unroll
    for (int a = 0; a < 2; a++)
        #pragma unroll
        for (int b = 0; b < 4; b++)
            #pragma unroll
            for (int c = 0; c < 4; c++) acc[a][b][c] = 0.f;

    for (int k0 = 0; k0 < K; k0 += 16) {
        #pragma unroll
        for (int i = 0; i < 8; i++) {
            int r = (tid >> 4) + i * 16, c = tid & 15;
            int row = bm0 + r, kk = k0 + c;
            float v = 0.f;
            if (row < M) {
                v = (kk < K1) ? A1[(size_t)row * K1 + kk]
                              : A2[(size_t)row * K2 + (kk - K1)];
                if (a_scale) v = fmaf(v, a_scale[kk], a_shift[kk]);
            }
            As[r][c] = to_tf32(v);
        }
        #pragma unroll
        for (int i = 0; i < 4; i++) {
            int c = tid & 63, r = (tid >> 6) + i * 4;
            int col = bn0 + c;
            Bs[r][c] = (col < N) ? to_tf32(B[(size_t)(k0 + r) * N + col]) : 0.f;
        }
        __syncthreads();
        #pragma unroll
        for (int ks = 0; ks < 2; ks++) {
            int kb = ks * 8 + lc;
            uint32_t af[2][4];
            #pragma unroll
            for (int mt = 0; mt < 2; mt++) {
                int row = warpM * 32 + mt * 16 + lr;
                af[mt][0] = __float_as_uint(As[row][kb]);
                af[mt][1] = __float_as_uint(As[row + 8][kb]);
                af[mt][2] = __float_as_uint(As[row][kb + 4]);
                af[mt][3] = __float_as_uint(As[row + 8][kb + 4]);
            }
            uint32_t bf[4][2];
            #pragma unroll
            for (int nt = 0; nt < 4; nt++) {
                int ncol = warpN * 32 + nt * 8 + lr;
                bf[nt][0] = __float_as_uint(Bs[ks * 8 + lc][ncol]);
                bf[nt][1] = __float_as_uint(Bs[ks * 8 + 4 + lc][ncol]);
            }
            #pragma unroll
            for (int mt = 0; mt < 2; mt++)
                #pragma unroll
                for (int nt = 0; nt < 4; nt++) {
                    asm volatile(
                        "mma.sync.aligned.m16n8k8.row.col.f32.tf32.tf32.f32 "
                        "{%0,%1,%2,%3}, {%4,%5,%6,%7}, {%8,%9}, {%0,%1,%2,%3};"
                        : "+f"(acc[mt][nt][0]), "+f"(acc[mt][nt][1]),
                          "+f"(acc[mt][nt][2]), "+f"(acc[mt][nt][3])
                        : "r"(af[mt][0]), "r"(af[mt][1]), "r"(af[mt][2]), "r"(af[mt][3]),
                          "r"(bf[nt][0]), "r"(bf[nt][1]));
                }
        }
        __syncthreads();
    }

    #pragma unroll
    for (int mt = 0; mt < 2; mt++) {
        int row0 = bm0 + warpM * 32 + mt * 16 + lr;
        #pragma unroll
        for (int nt = 0; nt < 4; nt++) {
            int col = bn0 + warpN * 32 + nt * 8 + 2 * lc;
            if (col < N) {
                float b0 = bias ? bias[col] : 0.f;
                float b1 = bias ? bias[col + 1] : 0.f;
                if (row0 < M) {
                    float v0 = acc[mt][nt][0] + b0;
                    float v1 = acc[mt][nt][1] + b1;
                    if (RELU) { v0 = fmaxf(v0, 0.f); v1 = fmaxf(v1, 0.f); }
                    C[(size_t)row0 * N + col] = v0;
                    C[(size_t)row0 * N + col + 1] = v1;
                }
                if (row0 + 8 < M) {
                    float v2 = acc[mt][nt][2] + b0;
                    float v3 = acc[mt][nt][3] + b1;
                    if (RELU) { v2 = fmaxf(v2, 0.f); v3 = fmaxf(v3, 0.f); }
                    C[(size_t)(row0 + 8) * N + col] = v2;
                    C[(size_t)(row0 + 8) * N + col + 1] = v3;
                }
            }
        }
    }
}

// ---------------- attention source/dest logits: warp per node ----------------
template<int HEADS>
__global__ void att_dots_kernel(const float* __restrict__ h,
                                const float* __restrict__ att_src,
                                const float* __restrict__ att_dst,
                                float* __restrict__ asrc, float* __restrict__ adst, int n)
{
    int warp = (blockIdx.x * blockDim.x + threadIdx.x) >> 5;
    int lane = threadIdx.x & 31;
    if (warp >= n) return;
    const float* row = h + (size_t)warp * (HEADS * 128);
    #pragma unroll
    for (int hd = 0; hd < HEADS; hd++) {
        float ss = 0.f, sd = 0.f;
        #pragma unroll
        for (int c = lane; c < 128; c += 32) {
            float v = row[hd * 128 + c];
            ss = fmaf(v, att_src[hd * 128 + c], ss);
            sd = fmaf(v, att_dst[hd * 128 + c], sd);
        }
        #pragma unroll
        for (int o = 16; o; o >>= 1) {
            ss += __shfl_xor_sync(0xffffffffu, ss, o);
            sd += __shfl_xor_sync(0xffffffffu, sd, o);
        }
        if (lane == 0) {
            asrc[warp * HEADS + hd] = ss;
            adst[warp * HEADS + hd] = sd;
        }
    }
}

// ---------------- fused per-node softmax aggregation (CSR, warp per node) ----------
template<int HEADS>
__global__ void agg_kernel(const float* __restrict__ h,
                           const float* __restrict__ asrc,
                           const float* __restrict__ adst,
                           const float* __restrict__ bias,
                           float* __restrict__ out, int n)
{
    int d = (int)((((size_t)blockIdx.x * blockDim.x) + threadIdx.x) >> 5);
    int lane = threadIdx.x & 31;
    if (d >= n) return;
    int r0 = g_row_ptr[d];
    int r1 = g_row_ptr[d + 1];

    float ad0, ad1 = 0.f;
    if (HEADS == 2) {
        float2 t = ((const float2*)adst)[d];
        ad0 = t.x; ad1 = t.y;
    } else {
        ad0 = adst[d];
    }

    // phase 1: per-head max over incident edges
    const float NEG_INF = __int_as_float(0xff800000);
    float m0 = NEG_INF, m1 = NEG_INF;
    for (int k = r0 + lane; k < r1; k += 32) {
        int s = g_csr_src[k];
        if (HEADS == 2) {
            float2 as2 = ((const float2*)asrc)[s];
            float a0 = as2.x + ad0;
            float a1 = as2.y + ad1;
            a0 = (a0 > 0.f) ? a0 : 0.2f * a0;
            a1 = (a1 > 0.f) ? a1 : 0.2f * a1;
            m0 = fmaxf(m0, a0);
            m1 = fmaxf(m1, a1);
        } else {
            float a0 = asrc[s] + ad0;
            a0 = (a0 > 0.f) ? a0 : 0.2f * a0;
            m0 = fmaxf(m0, a0);
        }
    }
    #pragma unroll
    for (int o = 16; o; o >>= 1) {
        m0 = fmaxf(m0, __shfl_xor_sync(0xffffffffu, m0, o));
        if (HEADS == 2) m1 = fmaxf(m1, __shfl_xor_sync(0xffffffffu, m1, o));
    }

    // phase 2: accumulate unnormalized weighted sum + partition sum
    const int CPL = HEADS * 128 / 32;     // 8 (conv1) or 4 (conv2)
    int c0 = lane * CPL;
    int hd = (HEADS == 2) ? (lane >> 4) : 0;
    float myad = (hd == 0) ? ad0 : ad1;
    float mym = (hd == 0) ? m0 : m1;

    float acc[CPL];
    #pragma unroll
    for (int j = 0; j < CPL; j++) acc[j] = 0.f;
    float ssum = 0.f;

    int k = r0;
    int sNext = g_csr_src[k];
    while (k < r1) {
        int s = sNext;
        k++;
        if (k < r1) sNext = g_csr_src[k];
        float a;
        if (HEADS == 2) {
            float2 as2 = ((const float2*)asrc)[s];
            a = ((hd == 0) ? as2.x : as2.y) + myad;
        } else {
            a = asrc[s] + myad;
        }
        a = (a > 0.f) ? a : 0.2f * a;
        float w = __expf(a - mym);
        ssum += w;
        const float4* hp = (const float4*)(h + (size_t)s * (HEADS * 128) + c0);
        #pragma unroll
        for (int v = 0; v < CPL / 4; v++) {
            float4 t = hp[v];
            acc[v * 4 + 0] = fmaf(w, t.x, acc[v * 4 + 0]);
            acc[v * 4 + 1] = fmaf(w, t.y, acc[v * 4 + 1]);
            acc[v * 4 + 2] = fmaf(w, t.z, acc[v * 4 + 2]);
            acc[v * 4 + 3] = fmaf(w, t.w, acc[v * 4 + 3]);
        }
    }

    float inv = 1.f / (ssum + 1e-16f);
    float* op = out + (size_t)d * (HEADS * 128) + c0;
    #pragma unroll
    for (int j = 0; j < CPL; j++)
        op[j] = fmaf(acc[j], inv, bias[c0 + j]);
}

// ---------------- batchnorm stats ----------------
__global__ void stats_cols_kernel(const float* __restrict__ y, int M, int ncols,
                                  float* __restrict__ stats)
{
    int col = threadIdx.x;          // blockDim.x == ncols
    float s = 0.f, ss = 0.f;
    for (int r = blockIdx.x; r < M; r += gridDim.x) {
        float v = y[(size_t)r * ncols + col];
        s += v; ss = fmaf(v, v, ss);
    }
    atomicAdd(&stats[col], s);
    atomicAdd(&stats[ncols + col], ss);
}

__global__ void bn_finalize_kernel(const float* __restrict__ stats,
                                   const float* __restrict__ gamma,
                                   const float* __restrict__ beta,
                                   float* __restrict__ scale, float* __restrict__ shift,
                                   int M, int ncols)
{
    int c = threadIdx.x;
    if (c >= ncols) return;
    float inv = 1.f / (float)M;
    float mu = stats[c] * inv;
    float var = stats[ncols + c] * inv - mu * mu;
    float sc = gamma[c] * rsqrtf(var + 1e-5f);
    scale[c] = sc;
    shift[c] = beta[c] - mu * sc;
}

// ---------------- fused last Linear (96->2) + relu + stats ----------------
__global__ void mlpb_kernel(const float* __restrict__ ya,
                            const float* __restrict__ scaleA,
                            const float* __restrict__ shiftA,
                            const float* __restrict__ Wb,
                            const float* __restrict__ bb,
                            float* __restrict__ yb,
                            float* __restrict__ stats, int M)
{
    __shared__ float w[192];
    __shared__ float sA[96], sS[96], bsh[2];
    int t = threadIdx.x;
    if (t < 192) w[t] = Wb[t];                  // [96,2] row-major
    if (t < 96) { sA[t] = scaleA[t]; sS[t] = shiftA[t]; }
    if (t < 2) bsh[t] = bb[t];
    __syncthreads();

    int r = blockIdx.x * blockDim.x + t;
    float y0 = 0.f, y1 = 0.f;
    if (r < M) {
        const float4* row = (const float4*)(ya + (size_t)r * 96);
        float acc0 = bsh[0], acc1 = bsh[1];
        #pragma unroll
        for (int v = 0; v < 24; v++) {
            float4 q = row[v];
            float vals[4] = {q.x, q.y, q.z, q.w};
            #pragma unroll
            for (int j = 0; j < 4; j++) {
                int c = v * 4 + j;
                float z = fmaf(vals[j], sA[c], sS[c]);
                acc0 = fmaf(z, w[c * 2], acc0);
                acc1 = fmaf(z, w[c * 2 + 1], acc1);
            }
        }
        y0 = fmaxf(acc0, 0.f);
        y1 = fmaxf(acc1, 0.f);
        yb[r * 2] = y0;
        yb[r * 2 + 1] = y1;
    }
    float s0 = y0, ss0 = y0 * y0, s1 = y1, ss1 = y1 * y1;
    #pragma unroll
    for (int o = 16; o; o >>= 1) {
        s0  += __shfl_xor_sync(0xffffffffu, s0, o);
        ss0 += __shfl_xor_sync(0xffffffffu, ss0, o);
        s1  += __shfl_xor_sync(0xffffffffu, s1, o);
        ss1 += __shfl_xor_sync(0xffffffffu, ss1, o);
    }
    if ((t & 31) == 0) {
        atomicAdd(&stats[0], s0);
        atomicAdd(&stats[1], s1);
        atomicAdd(&stats[2], ss0);
        atomicAdd(&stats[3], ss1);
    }
}

__global__ void final_kernel(const float* __restrict__ yb,
                             const float* __restrict__ scale,
                             const float* __restrict__ shift,
                             float* __restrict__ out, int total)
{
    int i = blockIdx.x * blockDim.x + threadIdx.x;
    if (i < total) {
        int c = i & 1;
        out[i] = fmaf(scale[c], yb[i], shift[c]);
    }
}

// ---------------- launch ----------------
static inline void* sym(const void* s) {
    void* p = nullptr;
    cudaGetSymbolAddress(&p, s);
    return p;
}

extern "C" void kernel_launch(void* const* d_in, const int* in_sizes, int n_in,
                              void* d_out, int out_size)
{
    const float* x        = (const float*)d_in[0];
    const void*  ei       = d_in[1];
    const float* W1       = (const float*)d_in[2];
    const float* att_src1 = (const float*)d_in[3];
    const float* att_dst1 = (const float*)d_in[4];
    const float* bias1    = (const float*)d_in[5];
    const float* W2       = (const float*)d_in[6];
    const float* att_src2 = (const float*)d_in[7];
    const float* att_dst2 = (const float*)d_in[8];
    const float* bias2    = (const float*)d_in[9];
    const float* Wl = (const float*)d_in[10];
    const float* bl = (const float*)d_in[11];
    const float* gl = (const float*)d_in[12];
    const float* betal = (const float*)d_in[13];
    const float* Wa = (const float*)d_in[14];
    const float* ba = (const float*)d_in[15];
    const float* ga = (const float*)d_in[16];
    const float* betaa = (const float*)d_in[17];
    const float* Wb = (const float*)d_in[18];
    const float* bb = (const float*)d_in[19];
    const float* gb = (const float*)d_in[20];
    const float* betab = (const float*)d_in[21];
    float* out = (float*)d_out;

    int n = in_sizes[0] / 128;      // 50000
    int E = in_sizes[1] / 2;        // 500000
    int Etot = E + n;
    int nblk = (n + 255) / 256;

    float* h1 = (float*)sym(g_h1);
    float* x1 = (float*)sym(g_x1);
    float* h2 = (float*)sym(g_h2);
    float* x2 = (float*)sym(g_x2);
    float* asrc1 = (float*)sym(g_asrc1);
    float* adst1 = (float*)sym(g_adst1);
    float* asrc2 = (float*)sym(g_asrc2);
    float* adst2 = (float*)sym(g_adst2);
    float* yl = (float*)sym(g_yl);
    float* ya = (float*)sym(g_ya);
    float* yb = (float*)sym(g_yb);
    float* statL = (float*)sym(g_statL);
    float* statA = (float*)sym(g_statA);
    float* statB = (float*)sym(g_statB);
    float* scaleL = (float*)sym(g_scaleL);
    float* shiftL = (float*)sym(g_shiftL);
    float* scaleA = (float*)sym(g_scaleA);
    float* shiftA = (float*)sym(g_shiftA);
    float* scaleB = (float*)sym(g_scaleB);
    float* shiftB = (float*)sym(g_shiftB);

    int edge_blocks = (Etot + 255) / 256;
    int warp_blocks = (n + 7) / 8;

    // Launch order arranged so profiled launch index 5 (-s 5 -c 1) = conv1 GEMM.
    // 0: detect + init
    detect_init_kernel<<<nblk, 256>>>((const int*)ei, n);
    // 1-4: CSR build prefix
    csr_count_kernel<<<edge_blocks, 256>>>(ei, E, n);       // 1
    block_sum_kernel<<<nblk, 256>>>(n);                      // 2
    scan_partials_kernel<<<1, 256>>>(nblk, Etot, n);         // 3
    scan_final_kernel<<<nblk, 256>>>(n);                     // 4

    // 5: conv1 GEMM (tf32 tensor cores)  <-- profiled launch
    {
        dim3 grid((256 + 63) / 64, (n + 127) / 128);
        gemm_tc<false><<<grid, 256>>>(x, 128, x, 128, W1, nullptr, nullptr, nullptr,
                                      h1, n, 256, 128);
    }
    // 6: finish CSR
    csr_fill_kernel<<<edge_blocks, 256>>>(ei, E, n);
    // 7-8: conv1 attention + aggregation
    att_dots_kernel<2><<<warp_blocks, 256>>>(h1, att_src1, att_dst1, asrc1, adst1, n);
    agg_kernel<2><<<warp_blocks, 256>>>(h1, asrc1, adst1, bias1, x1, n);

    // ---------- conv2 ----------
    {
        dim3 grid((128 + 63) / 64, (n + 127) / 128);
        gemm_tc<false><<<grid, 256>>>(x1, 256, x1, 256, W2, nullptr, nullptr, nullptr,
                                      h2, n, 128, 256);
    }
    att_dots_kernel<1><<<warp_blocks, 256>>>(h2, att_src2, att_dst2, asrc2, adst2, n);
    agg_kernel<1><<<warp_blocks, 256>>>(h2, asrc2, adst2, bias2, x2, n);

    // ---------- MLP head ----------
    {
        dim3 grid((96 + 63) / 64, (n + 127) / 128);
        gemm_tc<true><<<grid, 256>>>(x1, 256, x2, 128, Wl, bl, nullptr, nullptr,
                                     yl, n, 96, 384);
    }
    stats_cols_kernel<<<512, 96>>>(yl, n, 96, statL);
    bn_finalize_kernel<<<1, 96>>>(statL, gl, betal, scaleL, shiftL, n, 96);

    {
        dim3 grid((96 + 63) / 64, (n + 127) / 128);
        gemm_tc<true><<<grid, 256>>>(yl, 96, yl, 96, Wa, ba, scaleL, shiftL,
                                     ya, n, 96, 96);
    }
    stats_cols_kernel<<<512, 96>>>(ya, n, 96, statA);
    bn_finalize_kernel<<<1, 96>>>(statA, ga, betaa, scaleA, shiftA, n, 96);

    mlpb_kernel<<<(n + 255) / 256, 256>>>(ya, scaleA, shiftA, Wb, bb, yb, statB, n);
    bn_finalize_kernel<<<1, 2>>>(statB, gb, betab, scaleB, shiftB, n, 2);

    final_kernel<<<(n * 2 + 255) / 256, 256>>>(yb, scaleB, shiftB, out, n * 2);
}